// round 12
// baseline (speedup 1.0000x reference)
#include <cuda_runtime.h>
#include <cuda_fp16.h>
#include <math.h>
#include <stdint.h>
#include <stddef.h>

// ---------------------------------------------------------------------------
// LagunaMoE R11: fp16 mma m16n8k16, 128x256 tiles (512 thr / 16 warps),
// SwiGLU fused into gate_up epilogue via gate/up-interleaved weight layout.
// T=2048, H=2048, E=16, K=4, I=1408, IS=5632, scale=2.5, softcap=30
// ---------------------------------------------------------------------------

#define T_TOK 2048
#define HID   2048
#define NEXP  16
#define TOPK  4
#define IDIM  1408
#define ISH   5632

// -------------------- device scratch (static, allocation-free) -------------
__device__ __half g_sact [(size_t)T_TOK * ISH];              // shared act (half)
__device__ float  g_sdown[(size_t)T_TOK * HID];              // shared down out
__device__ __half g_ract [(size_t)T_TOK * TOPK * IDIM];      // routed act (half)
__device__ float  g_rdown[(size_t)T_TOK * TOPK * HID];

__device__ __half g_xh   [(size_t)T_TOK * HID];              // fp16 x
__device__ __half g_wgu_t[(size_t)NEXP * 2 * IDIM * HID];    // [E][2I][H] paired
__device__ __half g_wdn_t[(size_t)NEXP * HID * IDIM];        // [E][H][I]
__device__ __half g_sguT [(size_t)2 * ISH * HID];            // [2IS][H] paired
__device__ __half g_sdnT [(size_t)HID * ISH];                // [H][IS]

__device__ int   g_topk_ids[T_TOK * TOPK];
__device__ float g_topk_w  [T_TOK * TOPK];
__device__ int   g_counts[NEXP];
__device__ int   g_offs  [NEXP + 1];
__device__ int   g_cursor[NEXP];
__device__ int   g_perm  [T_TOK * TOPK];
__device__ int   g_rowof [T_TOK * TOPK];

// -------------------- PTX helpers ------------------------------------------
__device__ __forceinline__ void mma_f16(float* c, const uint32_t* a,
                                        uint32_t b0, uint32_t b1) {
    asm volatile(
        "mma.sync.aligned.m16n8k16.row.col.f32.f16.f16.f32 "
        "{%0,%1,%2,%3}, {%4,%5,%6,%7}, {%8,%9}, {%0,%1,%2,%3};"
        : "+f"(c[0]), "+f"(c[1]), "+f"(c[2]), "+f"(c[3])
        : "r"(a[0]), "r"(a[1]), "r"(a[2]), "r"(a[3]), "r"(b0), "r"(b1));
}
__device__ __forceinline__ void cp16(uint32_t dst, const void* src) {
    asm volatile("cp.async.cg.shared.global [%0], [%1], 16;\n" :: "r"(dst), "l"(src));
}
__device__ __forceinline__ void cp_commit() { asm volatile("cp.async.commit_group;\n"); }
__device__ __forceinline__ void cp_wait0()  { asm volatile("cp.async.wait_group 0;\n"); }
__device__ __forceinline__ void cp_wait1()  { asm volatile("cp.async.wait_group 1;\n"); }

// -------------------- small kernels ----------------------------------------
__global__ void zero_counts_kernel() {
    if (threadIdx.x < NEXP) g_counts[threadIdx.x] = 0;
}

__global__ __launch_bounds__(256) void router_kernel(
    const float* __restrict__ x, const float* __restrict__ gw,
    const float* __restrict__ bias)
{
    const int t = blockIdx.x;
    const float* xr = x + (size_t)t * HID;

    float acc[NEXP];
#pragma unroll
    for (int e = 0; e < NEXP; e++) acc[e] = 0.f;
    for (int h = threadIdx.x; h < HID; h += 256) {
        const float xv = xr[h];
#pragma unroll
        for (int e = 0; e < NEXP; e++)
            acc[e] = fmaf(xv, gw[e * HID + h], acc[e]);
    }
#pragma unroll
    for (int e = 0; e < NEXP; e++) {
        float v = acc[e];
#pragma unroll
        for (int off = 16; off > 0; off >>= 1)
            v += __shfl_xor_sync(0xffffffffu, v, off);
        acc[e] = v;
    }
    __shared__ float red[NEXP][8];
    __shared__ float s_score[NEXP], s_sel[NEXP];
    const int warp = threadIdx.x >> 5, lane = threadIdx.x & 31;
    if (lane == 0) {
#pragma unroll
        for (int e = 0; e < NEXP; e++) red[e][warp] = acc[e];
    }
    __syncthreads();
    if (threadIdx.x < NEXP) {
        float v = 0.f;
#pragma unroll
        for (int w = 0; w < 8; w++) v += red[threadIdx.x][w];
        v = tanhf(v * (1.0f / 30.0f)) * 30.0f;
        const float sc = 1.0f / (1.0f + expf(-v));
        s_score[threadIdx.x] = sc;
        s_sel[threadIdx.x]   = sc + bias[threadIdx.x];
    }
    __syncthreads();
    if (threadIdx.x == 0) {
        int ids[TOPK]; float ws[TOPK]; float wsum = 0.f;
        unsigned used = 0;
        for (int k = 0; k < TOPK; k++) {
            int best = 0; float bv = -1e30f;
            for (int e = 0; e < NEXP; e++)
                if (!((used >> e) & 1u) && s_sel[e] > bv) { bv = s_sel[e]; best = e; }
            used |= (1u << best);
            ids[k] = best; ws[k] = s_score[best]; wsum += s_score[best];
        }
        const float inv = 1.0f / wsum;
        for (int k = 0; k < TOPK; k++) {
            g_topk_ids[t * TOPK + k] = ids[k];
            g_topk_w  [t * TOPK + k] = ws[k] * inv;
            atomicAdd(&g_counts[ids[k]], 1);
        }
    }
}

__global__ void scan_kernel() {
    if (threadIdx.x == 0) {
        int s = 0;
        for (int e = 0; e < NEXP; e++) { g_offs[e] = s; s += g_counts[e]; g_cursor[e] = 0; }
        g_offs[NEXP] = s;
    }
}

__global__ void build_perm_kernel() {
    const int t = blockIdx.x * blockDim.x + threadIdx.x;
    if (t >= T_TOK) return;
    for (int k = 0; k < TOPK; k++) {
        const int e = g_topk_ids[t * TOPK + k];
        const int pos = g_offs[e] + atomicAdd(&g_cursor[e], 1);
        g_perm[pos] = t;
        g_rowof[t * TOPK + k] = pos;
    }
}

// Convert x to fp16
__global__ void cvt_x_kernel(const float* __restrict__ x) {
    const int i = blockIdx.x * 256 + threadIdx.x;
    g_xh[i] = __float2half_rn(x[i]);
}

// Transpose [R, C] f32 -> [C', R] fp16. If pairHalf > 0, the output row index
// is remapped n -> (n < pairHalf) ? 2n : 2(n-pairHalf)+1, interleaving
// gate/up neuron rows so the GEMM tile's even/odd columns form (gate, up).
__global__ __launch_bounds__(256) void transpose_h_kernel(
    const float* __restrict__ in, __half* __restrict__ out,
    int R, int C, size_t inStride, size_t outStride, int pairHalf)
{
    in  += (size_t)blockIdx.z * inStride;
    out += (size_t)blockIdx.z * outStride;
    __shared__ float tile[32][33];
    const int c0 = blockIdx.x * 32, r0 = blockIdx.y * 32;
    const int tx = threadIdx.x, ty = threadIdx.y;   // block (32, 8)
#pragma unroll
    for (int i = ty; i < 32; i += 8)
        tile[i][tx] = in[(size_t)(r0 + i) * C + c0 + tx];
    __syncthreads();
#pragma unroll
    for (int i = ty; i < 32; i += 8) {
        int n = c0 + i;
        if (pairHalf > 0) n = (n < pairHalf) ? (2 * n) : (2 * (n - pairHalf) + 1);
        out[(size_t)n * R + r0 + tx] = __float2half_rn(tile[tx][i]);
    }
}

// -------------------- fp16 mma GEMM, 128x256 tile, 16 warps ----------------
// C[M,N] = A[M,K] @ Bt[N,K]^T   (A, Bt fp16)
// MODE 0: plain; 1: grouped (blockIdx.z = expert); 2: grouped + perm-indirect A.
// ACT 0: write f32 C. ACT 1: fused SwiGLU epilogue — B rows are
// gate/up-interleaved, so acc col pairs (even, odd) = (g, u); writes
// half act at column index n/2 with row stride ldc.
// Warp grid 4x4 (mw=(w&3)*32, nw=(w>>2)*64), warp tile 32x64, BK=16.
// smem rows stride 24 halfs (48 B). 3 stages x 384 rows = 55296 B.
#define ROW_HALFS   24
#define A_ROWS      128
#define B_ROWS      256
#define TILE_ROWS   (A_ROWS + B_ROWS)          // 384
#define STAGE_HALFS (TILE_ROWS * ROW_HALFS)    // 9216
#define STAGE_BYTES (STAGE_HALFS * 2)          // 18432
#define GEMM_SMEM_BYTES (3 * STAGE_BYTES)      // 55296

template <int MODE, int ACT>
__global__ __launch_bounds__(512, 1) void gemm_mma_kernel(
    const __half* __restrict__ A, int K,
    const __half* __restrict__ Bt, size_t btstride,
    float* __restrict__ C, __half* __restrict__ actC, int ldc, int M)
{
    int rowOff = 0, Mloc = M;
    const __half* Bp = Bt;
    if (MODE >= 1) {
        const int e = blockIdx.z;
        rowOff = g_offs[e];
        Mloc = g_offs[e + 1] - rowOff;
        Bp += (size_t)e * btstride;
    }
    const int m0 = blockIdx.y * 128;
    if (m0 >= Mloc) return;
    const int n0 = blockIdx.x * 256;

    extern __shared__ __half smh[];

    const int tid = threadIdx.x;
    const int l   = tid & 31;
    const int wid = tid >> 5;          // 0..15
    const int mw  = (wid & 3) * 32;    // warp m offset
    const int nw  = (wid >> 2) * 64;   // warp n offset

    // ---- staging: 384 rows x 2 chunks(16B) = 768 chunks over 512 threads ---
    // chunk0 = tid        -> row tid>>1      (A rows 0..127, B rows 0..127)
    // chunk1 = 512+tid    -> row 256+(tid>>1) (B rows 128..255), tid < 256 only
    const int r0c  = tid >> 1;
    const int h0c  = tid & 1;
    const __half* ptr0;
    if (r0c < A_ROWS) {
        const int rA = m0 + r0c;
        const int rCl = (rA < Mloc) ? rA : (Mloc - 1);
        if (MODE == 2)      ptr0 = A + (size_t)g_perm[rowOff + rCl] * K;
        else if (MODE == 1) ptr0 = A + (size_t)(rowOff + rCl) * K;
        else                ptr0 = A + (size_t)rCl * K;
    } else {
        ptr0 = Bp + (size_t)(n0 + (r0c - A_ROWS)) * K;
    }
    ptr0 += h0c * 8;
    const __half* ptr1 = (tid < 256)
        ? Bp + (size_t)(n0 + 128 + (tid >> 1)) * K + (tid & 1) * 8
        : (const __half*)0;

    const uint32_t smem_base = (uint32_t)__cvta_generic_to_shared(smh);
    const uint32_t dst0 = smem_base + (uint32_t)(r0c * ROW_HALFS + h0c * 8) * 2;
    const uint32_t dst1 = smem_base +
        (uint32_t)((256 + (tid >> 1)) * ROW_HALFS + (tid & 1) * 8) * 2;

    float acc[2][8][4];
#pragma unroll
    for (int i = 0; i < 2; i++)
#pragma unroll
        for (int j = 0; j < 8; j++)
#pragma unroll
            for (int q = 0; q < 4; q++) acc[i][j][q] = 0.f;

    const int S = K >> 4;   // K16 stages

    auto stage = [&](int buf, int slab) {
        const uint32_t so = (uint32_t)buf * STAGE_BYTES;
        cp16(dst0 + so, ptr0 + (size_t)slab * 16);
        if (tid < 256) cp16(dst1 + so, ptr1 + (size_t)slab * 16);
        cp_commit();
    };

    stage(0, 0);
    if (S > 1) stage(1, 1);

    // ldmatrix lane->address maps
    const int aRowSel = l & 15;
    const int aKoff   = (l & 16) ? 8 : 0;
    const int bRowSel = (l & 7) + ((l & 16) ? 8 : 0);
    const int bKoff   = (l & 8) ? 8 : 0;

    for (int kt = 0; kt < S; ++kt) {
        if (kt == S - 1) cp_wait0(); else cp_wait1();
        __syncthreads();
        const int buf = kt % 3;
        if (kt + 2 < S) stage((kt + 2) % 3, kt + 2);

        const __half* AsBuf = smh + buf * STAGE_HALFS;
        const __half* BsBuf = AsBuf + A_ROWS * ROW_HALFS;

        uint32_t bfr[4][4];
#pragma unroll
        for (int j = 0; j < 4; j++) {
            uint32_t addr = (uint32_t)__cvta_generic_to_shared(
                BsBuf + (nw + 16 * j + bRowSel) * ROW_HALFS + bKoff);
            asm volatile(
                "ldmatrix.sync.aligned.m8n8.x4.shared.b16 {%0,%1,%2,%3}, [%4];"
                : "=r"(bfr[j][0]), "=r"(bfr[j][1]), "=r"(bfr[j][2]), "=r"(bfr[j][3])
                : "r"(addr));
        }
        uint32_t a[2][4];
#pragma unroll
        for (int i = 0; i < 2; i++) {
            uint32_t addr = (uint32_t)__cvta_generic_to_shared(
                AsBuf + (mw + 16 * i + aRowSel) * ROW_HALFS + aKoff);
            asm volatile(
                "ldmatrix.sync.aligned.m8n8.x4.shared.b16 {%0,%1,%2,%3}, [%4];"
                : "=r"(a[i][0]), "=r"(a[i][1]), "=r"(a[i][2]), "=r"(a[i][3])
                : "r"(addr));
        }
#pragma unroll
        for (int i = 0; i < 2; i++)
#pragma unroll
            for (int j = 0; j < 4; j++) {
                mma_f16(acc[i][2 * j],     a[i], bfr[j][0], bfr[j][1]);
                mma_f16(acc[i][2 * j + 1], a[i], bfr[j][2], bfr[j][3]);
            }
        __syncthreads();
    }

    // ---- epilogue ----
    if (ACT) {
#pragma unroll
        for (int i = 0; i < 2; i++) {
            const int r0 = m0 + mw + 16 * i + (l >> 2);
            const int r1 = r0 + 8;
            const int ac = ((n0 + nw) >> 1) + (l & 3);
            __half* a0 = actC + (size_t)(rowOff + r0) * ldc + ac;
            __half* a1 = actC + (size_t)(rowOff + r1) * ldc + ac;
#pragma unroll
            for (int j = 0; j < 8; j++) {
                if (r0 < Mloc) {
                    const float g = acc[i][j][0], u = acc[i][j][1];
                    a0[4 * j] = __float2half_rn((g / (1.0f + expf(-g))) * u);
                }
                if (r1 < Mloc) {
                    const float g = acc[i][j][2], u = acc[i][j][3];
                    a1[4 * j] = __float2half_rn((g / (1.0f + expf(-g))) * u);
                }
            }
        }
    } else {
#pragma unroll
        for (int i = 0; i < 2; i++) {
            const int r0 = m0 + mw + 16 * i + (l >> 2);
            const int r1 = r0 + 8;
            const int colb = n0 + nw + 2 * (l & 3);
            if (r0 < Mloc) {
                float* cp = C + (size_t)(rowOff + r0) * ldc + colb;
#pragma unroll
                for (int j = 0; j < 8; j++)
                    *(float2*)(cp + 8 * j) = make_float2(acc[i][j][0], acc[i][j][1]);
            }
            if (r1 < Mloc) {
                float* cp = C + (size_t)(rowOff + r1) * ldc + colb;
#pragma unroll
                for (int j = 0; j < 8; j++)
                    *(float2*)(cp + 8 * j) = make_float2(acc[i][j][2], acc[i][j][3]);
            }
        }
    }
}

// -------------------- combine ----------------------------------------------
__global__ void combine_kernel(float* __restrict__ out, const float* __restrict__ sdown)
{
    const int idx = blockIdx.x * 256 + threadIdx.x;
    const int t = idx >> 11;
    const int h = idx & (HID - 1);
    float r = 0.f;
#pragma unroll
    for (int k = 0; k < TOPK; k++) {
        const int pos = g_rowof[t * TOPK + k];
        r = fmaf(g_topk_w[t * TOPK + k], g_rdown[(size_t)pos * HID + h], r);
    }
    out[idx] = fmaf(2.5f, r, sdown[idx]);
}

// -------------------- launch -----------------------------------------------
extern "C" void kernel_launch(void* const* d_in, const int* in_sizes, int n_in,
                              void* d_out, int out_size)
{
    const float* x    = (const float*)d_in[0];   // [T, H]
    const float* gw   = (const float*)d_in[1];   // [E, H]
    const float* cb   = (const float*)d_in[2];   // [E]
    const float* wgu  = (const float*)d_in[3];   // [E, H, 2I]
    const float* wdn  = (const float*)d_in[4];   // [E, I, H]
    const float* swgu = (const float*)d_in[5];   // [H, 2*IS]
    const float* swdn = (const float*)d_in[6];   // [IS, H]
    float* out = (float*)d_out;
    (void)in_sizes; (void)n_in; (void)out_size;

    float  *p_sdown, *p_rdown;
    __half *p_sact, *p_ract, *p_xh, *p_wguT, *p_wdnT, *p_sguT, *p_sdnT;
    cudaGetSymbolAddress((void**)&p_sact,  g_sact);
    cudaGetSymbolAddress((void**)&p_sdown, g_sdown);
    cudaGetSymbolAddress((void**)&p_ract,  g_ract);
    cudaGetSymbolAddress((void**)&p_rdown, g_rdown);
    cudaGetSymbolAddress((void**)&p_xh,    g_xh);
    cudaGetSymbolAddress((void**)&p_wguT,  g_wgu_t);
    cudaGetSymbolAddress((void**)&p_wdnT,  g_wdn_t);
    cudaGetSymbolAddress((void**)&p_sguT,  g_sguT);
    cudaGetSymbolAddress((void**)&p_sdnT,  g_sdnT);

    cudaFuncSetAttribute(gemm_mma_kernel<2, 1>,
        cudaFuncAttributeMaxDynamicSharedMemorySize, GEMM_SMEM_BYTES);
    cudaFuncSetAttribute(gemm_mma_kernel<1, 0>,
        cudaFuncAttributeMaxDynamicSharedMemorySize, GEMM_SMEM_BYTES);
    cudaFuncSetAttribute(gemm_mma_kernel<0, 1>,
        cudaFuncAttributeMaxDynamicSharedMemorySize, GEMM_SMEM_BYTES);
    cudaFuncSetAttribute(gemm_mma_kernel<0, 0>,
        cudaFuncAttributeMaxDynamicSharedMemorySize, GEMM_SMEM_BYTES);

    // ---- routing ----
    zero_counts_kernel<<<1, 32>>>();
    router_kernel<<<T_TOK, 256>>>(x, gw, cb);
    scan_kernel<<<1, 32>>>();
    build_perm_kernel<<<(T_TOK + 255) / 256, 256>>>();

    // ---- precondition: x -> fp16; weight transposes (gate_up paired) ----
    cvt_x_kernel<<<(T_TOK * HID) / 256, 256>>>(x);
    transpose_h_kernel<<<dim3(2 * IDIM / 32, HID / 32, NEXP), dim3(32, 8)>>>(
        wgu, p_wguT, HID, 2 * IDIM, (size_t)HID * 2 * IDIM, (size_t)HID * 2 * IDIM, IDIM);
    transpose_h_kernel<<<dim3(HID / 32, IDIM / 32, NEXP), dim3(32, 8)>>>(
        wdn, p_wdnT, IDIM, HID, (size_t)IDIM * HID, (size_t)IDIM * HID, 0);
    transpose_h_kernel<<<dim3(2 * ISH / 32, HID / 32, 1), dim3(32, 8)>>>(
        swgu, p_sguT, HID, 2 * ISH, 0, 0, ISH);
    transpose_h_kernel<<<dim3(HID / 32, ISH / 32, 1), dim3(32, 8)>>>(
        swdn, p_sdnT, ISH, HID, 0, 0, 0);

    // ---- routed experts ----
    // gate_up + fused SwiGLU -> g_ract (half)
    gemm_mma_kernel<2, 1><<<dim3(2 * IDIM / 256, 16, NEXP), 512, GEMM_SMEM_BYTES>>>(
        p_xh, HID, p_wguT, (size_t)2 * IDIM * HID, nullptr, p_ract, IDIM, 0);
    // down -> g_rdown (f32)
    gemm_mma_kernel<1, 0><<<dim3(HID / 256, 16, NEXP), 512, GEMM_SMEM_BYTES>>>(
        p_ract, IDIM, p_wdnT, (size_t)HID * IDIM, p_rdown, nullptr, HID, 0);

    // ---- shared expert ----
    gemm_mma_kernel<0, 1><<<dim3(2 * ISH / 256, T_TOK / 128, 1), 512, GEMM_SMEM_BYTES>>>(
        p_xh, HID, p_sguT, 0, nullptr, p_sact, ISH, T_TOK);
    gemm_mma_kernel<0, 0><<<dim3(HID / 256, T_TOK / 128, 1), 512, GEMM_SMEM_BYTES>>>(
        p_sact, ISH, p_sdnT, 0, p_sdown, nullptr, HID, T_TOK);

    // ---- combine: out = 2.5 * routed + shared ----
    combine_kernel<<<(T_TOK * HID) / 256, 256>>>(out, p_sdown);
}

// round 14
// speedup vs baseline: 1.1827x; 1.1827x over previous
#include <cuda_runtime.h>
#include <cuda_fp16.h>
#include <math.h>
#include <stdint.h>
#include <stddef.h>

// ---------------------------------------------------------------------------
// LagunaMoE R12: R10 GEMM (fp16 m16n8k16, 128x128, 256thr, 2 CTA/SM) +
// fused SwiGLU epilogue via gate/up-paired weight layout (R11's fusion only).
// T=2048, H=2048, E=16, K=4, I=1408, IS=5632, scale=2.5, softcap=30
// ---------------------------------------------------------------------------

#define T_TOK 2048
#define HID   2048
#define NEXP  16
#define TOPK  4
#define IDIM  1408
#define ISH   5632

// -------------------- device scratch (static, allocation-free) -------------
__device__ __half g_sact [(size_t)T_TOK * ISH];              // shared act (half)
__device__ float  g_sdown[(size_t)T_TOK * HID];              // shared down out
__device__ __half g_ract [(size_t)T_TOK * TOPK * IDIM];      // routed act (half)
__device__ float  g_rdown[(size_t)T_TOK * TOPK * HID];

__device__ __half g_xh   [(size_t)T_TOK * HID];              // fp16 x
__device__ __half g_wgu_t[(size_t)NEXP * 2 * IDIM * HID];    // [E][2I][H] paired
__device__ __half g_wdn_t[(size_t)NEXP * HID * IDIM];        // [E][H][I]
__device__ __half g_sguT [(size_t)2 * ISH * HID];            // [2IS][H] paired
__device__ __half g_sdnT [(size_t)HID * ISH];                // [H][IS]

__device__ int   g_topk_ids[T_TOK * TOPK];
__device__ float g_topk_w  [T_TOK * TOPK];
__device__ int   g_counts[NEXP];
__device__ int   g_offs  [NEXP + 1];
__device__ int   g_cursor[NEXP];
__device__ int   g_perm  [T_TOK * TOPK];
__device__ int   g_rowof [T_TOK * TOPK];

// -------------------- PTX helpers ------------------------------------------
__device__ __forceinline__ void mma_f16(float* c, const uint32_t* a,
                                        uint32_t b0, uint32_t b1) {
    asm volatile(
        "mma.sync.aligned.m16n8k16.row.col.f32.f16.f16.f32 "
        "{%0,%1,%2,%3}, {%4,%5,%6,%7}, {%8,%9}, {%0,%1,%2,%3};"
        : "+f"(c[0]), "+f"(c[1]), "+f"(c[2]), "+f"(c[3])
        : "r"(a[0]), "r"(a[1]), "r"(a[2]), "r"(a[3]), "r"(b0), "r"(b1));
}
__device__ __forceinline__ void cp16(uint32_t dst, const void* src) {
    asm volatile("cp.async.cg.shared.global [%0], [%1], 16;\n" :: "r"(dst), "l"(src));
}
__device__ __forceinline__ void cp_commit() { asm volatile("cp.async.commit_group;\n"); }
__device__ __forceinline__ void cp_wait0()  { asm volatile("cp.async.wait_group 0;\n"); }
__device__ __forceinline__ void cp_wait1()  { asm volatile("cp.async.wait_group 1;\n"); }

// -------------------- small kernels ----------------------------------------
__global__ void zero_counts_kernel() {
    if (threadIdx.x < NEXP) g_counts[threadIdx.x] = 0;
}

__global__ __launch_bounds__(256) void router_kernel(
    const float* __restrict__ x, const float* __restrict__ gw,
    const float* __restrict__ bias)
{
    const int t = blockIdx.x;
    const float* xr = x + (size_t)t * HID;

    float acc[NEXP];
#pragma unroll
    for (int e = 0; e < NEXP; e++) acc[e] = 0.f;
    for (int h = threadIdx.x; h < HID; h += 256) {
        const float xv = xr[h];
#pragma unroll
        for (int e = 0; e < NEXP; e++)
            acc[e] = fmaf(xv, gw[e * HID + h], acc[e]);
    }
#pragma unroll
    for (int e = 0; e < NEXP; e++) {
        float v = acc[e];
#pragma unroll
        for (int off = 16; off > 0; off >>= 1)
            v += __shfl_xor_sync(0xffffffffu, v, off);
        acc[e] = v;
    }
    __shared__ float red[NEXP][8];
    __shared__ float s_score[NEXP], s_sel[NEXP];
    const int warp = threadIdx.x >> 5, lane = threadIdx.x & 31;
    if (lane == 0) {
#pragma unroll
        for (int e = 0; e < NEXP; e++) red[e][warp] = acc[e];
    }
    __syncthreads();
    if (threadIdx.x < NEXP) {
        float v = 0.f;
#pragma unroll
        for (int w = 0; w < 8; w++) v += red[threadIdx.x][w];
        v = tanhf(v * (1.0f / 30.0f)) * 30.0f;
        const float sc = 1.0f / (1.0f + expf(-v));
        s_score[threadIdx.x] = sc;
        s_sel[threadIdx.x]   = sc + bias[threadIdx.x];
    }
    __syncthreads();
    if (threadIdx.x == 0) {
        int ids[TOPK]; float ws[TOPK]; float wsum = 0.f;
        unsigned used = 0;
        for (int k = 0; k < TOPK; k++) {
            int best = 0; float bv = -1e30f;
            for (int e = 0; e < NEXP; e++)
                if (!((used >> e) & 1u) && s_sel[e] > bv) { bv = s_sel[e]; best = e; }
            used |= (1u << best);
            ids[k] = best; ws[k] = s_score[best]; wsum += s_score[best];
        }
        const float inv = 1.0f / wsum;
        for (int k = 0; k < TOPK; k++) {
            g_topk_ids[t * TOPK + k] = ids[k];
            g_topk_w  [t * TOPK + k] = ws[k] * inv;
            atomicAdd(&g_counts[ids[k]], 1);
        }
    }
}

__global__ void scan_kernel() {
    if (threadIdx.x == 0) {
        int s = 0;
        for (int e = 0; e < NEXP; e++) { g_offs[e] = s; s += g_counts[e]; g_cursor[e] = 0; }
        g_offs[NEXP] = s;
    }
}

__global__ void build_perm_kernel() {
    const int t = blockIdx.x * blockDim.x + threadIdx.x;
    if (t >= T_TOK) return;
    for (int k = 0; k < TOPK; k++) {
        const int e = g_topk_ids[t * TOPK + k];
        const int pos = g_offs[e] + atomicAdd(&g_cursor[e], 1);
        g_perm[pos] = t;
        g_rowof[t * TOPK + k] = pos;
    }
}

// Convert x to fp16
__global__ void cvt_x_kernel(const float* __restrict__ x) {
    const int i = blockIdx.x * 256 + threadIdx.x;
    g_xh[i] = __float2half_rn(x[i]);
}

// Transpose [R, C] f32 -> [C', R] fp16. If pairHalf > 0, output row index is
// remapped n -> (n < pairHalf) ? 2n : 2(n-pairHalf)+1 (gate/up interleave).
__global__ __launch_bounds__(256) void transpose_h_kernel(
    const float* __restrict__ in, __half* __restrict__ out,
    int R, int C, size_t inStride, size_t outStride, int pairHalf)
{
    in  += (size_t)blockIdx.z * inStride;
    out += (size_t)blockIdx.z * outStride;
    __shared__ float tile[32][33];
    const int c0 = blockIdx.x * 32, r0 = blockIdx.y * 32;
    const int tx = threadIdx.x, ty = threadIdx.y;   // block (32, 8)
#pragma unroll
    for (int i = ty; i < 32; i += 8)
        tile[i][tx] = in[(size_t)(r0 + i) * C + c0 + tx];
    __syncthreads();
#pragma unroll
    for (int i = ty; i < 32; i += 8) {
        int n = c0 + i;
        if (pairHalf > 0) n = (n < pairHalf) ? (2 * n) : (2 * (n - pairHalf) + 1);
        out[(size_t)n * R + r0 + tx] = __float2half_rn(tile[tx][i]);
    }
}

// -------------------- fp16 mma GEMM, 128x128 tile, 8 warps -----------------
// C[M,N] = A[M,K] @ Bt[N,K]^T   (A, Bt fp16)
// MODE 0: plain; 1: grouped (blockIdx.z = expert); 2: grouped + perm-indirect A.
// ACT 0: write f32 C. ACT 1: fused SwiGLU epilogue — B rows gate/up-paired,
// acc col pairs (even, odd) = (g, u); writes half act at column n/2, stride ldc.
// Warp grid 4x2 (mw=(w&3)*32, nw=(w>>2)*64), warp tile 32x64, BK=16.
// smem rows stride 24 halfs. 3 stages x 256 rows x 48 B = 36864 B.
#define ROW_HALFS   24
#define A_HALFS     (128 * ROW_HALFS)          // 3072
#define STAGE_HALFS (2 * A_HALFS)              // 6144
#define STAGE_BYTES (STAGE_HALFS * 2)          // 12288
#define GEMM_SMEM_BYTES (3 * STAGE_BYTES)      // 36864

template <int MODE, int ACT>
__global__ __launch_bounds__(256, 2) void gemm_mma_kernel(
    const __half* __restrict__ A, int K,
    const __half* __restrict__ Bt, size_t btstride,
    float* __restrict__ C, __half* __restrict__ actC, int ldc, int M)
{
    int rowOff = 0, Mloc = M;
    const __half* Bp = Bt;
    if (MODE >= 1) {
        const int e = blockIdx.z;
        rowOff = g_offs[e];
        Mloc = g_offs[e + 1] - rowOff;
        Bp += (size_t)e * btstride;
    }
    const int m0 = blockIdx.y * 128;
    if (m0 >= Mloc) return;
    const int n0 = blockIdx.x * 128;

    extern __shared__ __half smh[];

    const int tid = threadIdx.x;
    const int l   = tid & 31;
    const int wid = tid >> 5;          // 0..7
    const int mw  = (wid & 3) * 32;    // warp m offset
    const int nw  = (wid >> 2) * 64;   // warp n offset

    // ---- staging: 2 threads per row; 16B chunk each ----
    const int sRow  = tid >> 1;
    const int sHalf = tid & 1;
    const int rA  = m0 + sRow;
    const int rCl = (rA < Mloc) ? rA : (Mloc - 1);
    const __half* aRowPtr;
    if (MODE == 2)      aRowPtr = A + (size_t)g_perm[rowOff + rCl] * K;
    else if (MODE == 1) aRowPtr = A + (size_t)(rowOff + rCl) * K;
    else                aRowPtr = A + (size_t)rCl * K;
    aRowPtr += sHalf * 8;
    const __half* bRowPtr = Bp + (size_t)(n0 + sRow) * K + sHalf * 8;

    const uint32_t smem_base = (uint32_t)__cvta_generic_to_shared(smh);
    const uint32_t aDst = smem_base + (uint32_t)(sRow * ROW_HALFS + sHalf * 8) * 2;
    const uint32_t bDst = aDst + A_HALFS * 2;

    float acc[2][8][4];
#pragma unroll
    for (int i = 0; i < 2; i++)
#pragma unroll
        for (int j = 0; j < 8; j++)
#pragma unroll
            for (int q = 0; q < 4; q++) acc[i][j][q] = 0.f;

    const int S = K >> 4;

    auto stage = [&](int buf, int slab) {
        const uint32_t so = (uint32_t)buf * STAGE_BYTES;
        cp16(aDst + so, aRowPtr + (size_t)slab * 16);
        cp16(bDst + so, bRowPtr + (size_t)slab * 16);
        cp_commit();
    };

    stage(0, 0);
    if (S > 1) stage(1, 1);

    const int aRowSel = l & 15;
    const int aKoff   = (l & 16) ? 8 : 0;
    const int bRowSel = (l & 7) + ((l & 16) ? 8 : 0);
    const int bKoff   = (l & 8) ? 8 : 0;

    for (int kt = 0; kt < S; ++kt) {
        if (kt == S - 1) cp_wait0(); else cp_wait1();
        __syncthreads();
        const int buf = kt % 3;
        if (kt + 2 < S) stage((kt + 2) % 3, kt + 2);

        const __half* AsBuf = smh + buf * STAGE_HALFS;
        const __half* BsBuf = AsBuf + A_HALFS;

        uint32_t bfr[4][4];
#pragma unroll
        for (int j = 0; j < 4; j++) {
            uint32_t addr = (uint32_t)__cvta_generic_to_shared(
                BsBuf + (nw + 16 * j + bRowSel) * ROW_HALFS + bKoff);
            asm volatile(
                "ldmatrix.sync.aligned.m8n8.x4.shared.b16 {%0,%1,%2,%3}, [%4];"
                : "=r"(bfr[j][0]), "=r"(bfr[j][1]), "=r"(bfr[j][2]), "=r"(bfr[j][3])
                : "r"(addr));
        }
        uint32_t a[2][4];
#pragma unroll
        for (int i = 0; i < 2; i++) {
            uint32_t addr = (uint32_t)__cvta_generic_to_shared(
                AsBuf + (mw + 16 * i + aRowSel) * ROW_HALFS + aKoff);
            asm volatile(
                "ldmatrix.sync.aligned.m8n8.x4.shared.b16 {%0,%1,%2,%3}, [%4];"
                : "=r"(a[i][0]), "=r"(a[i][1]), "=r"(a[i][2]), "=r"(a[i][3])
                : "r"(addr));
        }
#pragma unroll
        for (int i = 0; i < 2; i++)
#pragma unroll
            for (int j = 0; j < 4; j++) {
                mma_f16(acc[i][2 * j],     a[i], bfr[j][0], bfr[j][1]);
                mma_f16(acc[i][2 * j + 1], a[i], bfr[j][2], bfr[j][3]);
            }
        __syncthreads();
    }

    // ---- epilogue ----
    if (ACT) {
        // col pair (2c, 2c+1) = (gate, up) -> act col = c, c = (n0+nw)/2+(l&3)+4j
#pragma unroll
        for (int i = 0; i < 2; i++) {
            const int r0 = m0 + mw + 16 * i + (l >> 2);
            const int r1 = r0 + 8;
            const int ac = ((n0 + nw) >> 1) + (l & 3);
            __half* a0 = actC + (size_t)(rowOff + r0) * ldc + ac;
            __half* a1 = actC + (size_t)(rowOff + r1) * ldc + ac;
#pragma unroll
            for (int j = 0; j < 8; j++) {
                if (r0 < Mloc) {
                    const float g = acc[i][j][0], u = acc[i][j][1];
                    a0[4 * j] = __float2half_rn((g / (1.0f + expf(-g))) * u);
                }
                if (r1 < Mloc) {
                    const float g = acc[i][j][2], u = acc[i][j][3];
                    a1[4 * j] = __float2half_rn((g / (1.0f + expf(-g))) * u);
                }
            }
        }
    } else {
#pragma unroll
        for (int i = 0; i < 2; i++) {
            const int r0 = m0 + mw + 16 * i + (l >> 2);
            const int r1 = r0 + 8;
            const int colb = n0 + nw + 2 * (l & 3);
            if (r0 < Mloc) {
                float* cp = C + (size_t)(rowOff + r0) * ldc + colb;
#pragma unroll
                for (int j = 0; j < 8; j++)
                    *(float2*)(cp + 8 * j) = make_float2(acc[i][j][0], acc[i][j][1]);
            }
            if (r1 < Mloc) {
                float* cp = C + (size_t)(rowOff + r1) * ldc + colb;
#pragma unroll
                for (int j = 0; j < 8; j++)
                    *(float2*)(cp + 8 * j) = make_float2(acc[i][j][2], acc[i][j][3]);
            }
        }
    }
}

// -------------------- combine ----------------------------------------------
__global__ void combine_kernel(float* __restrict__ out, const float* __restrict__ sdown)
{
    const int idx = blockIdx.x * 256 + threadIdx.x;
    const int t = idx >> 11;
    const int h = idx & (HID - 1);
    float r = 0.f;
#pragma unroll
    for (int k = 0; k < TOPK; k++) {
        const int pos = g_rowof[t * TOPK + k];
        r = fmaf(g_topk_w[t * TOPK + k], g_rdown[(size_t)pos * HID + h], r);
    }
    out[idx] = fmaf(2.5f, r, sdown[idx]);
}

// -------------------- launch -----------------------------------------------
extern "C" void kernel_launch(void* const* d_in, const int* in_sizes, int n_in,
                              void* d_out, int out_size)
{
    const float* x    = (const float*)d_in[0];   // [T, H]
    const float* gw   = (const float*)d_in[1];   // [E, H]
    const float* cb   = (const float*)d_in[2];   // [E]
    const float* wgu  = (const float*)d_in[3];   // [E, H, 2I]
    const float* wdn  = (const float*)d_in[4];   // [E, I, H]
    const float* swgu = (const float*)d_in[5];   // [H, 2*IS]
    const float* swdn = (const float*)d_in[6];   // [IS, H]
    float* out = (float*)d_out;
    (void)in_sizes; (void)n_in; (void)out_size;

    float  *p_sdown, *p_rdown;
    __half *p_sact, *p_ract, *p_xh, *p_wguT, *p_wdnT, *p_sguT, *p_sdnT;
    cudaGetSymbolAddress((void**)&p_sact,  g_sact);
    cudaGetSymbolAddress((void**)&p_sdown, g_sdown);
    cudaGetSymbolAddress((void**)&p_ract,  g_ract);
    cudaGetSymbolAddress((void**)&p_rdown, g_rdown);
    cudaGetSymbolAddress((void**)&p_xh,    g_xh);
    cudaGetSymbolAddress((void**)&p_wguT,  g_wgu_t);
    cudaGetSymbolAddress((void**)&p_wdnT,  g_wdn_t);
    cudaGetSymbolAddress((void**)&p_sguT,  g_sguT);
    cudaGetSymbolAddress((void**)&p_sdnT,  g_sdnT);

    cudaFuncSetAttribute(gemm_mma_kernel<2, 1>,
        cudaFuncAttributeMaxDynamicSharedMemorySize, GEMM_SMEM_BYTES);
    cudaFuncSetAttribute(gemm_mma_kernel<1, 0>,
        cudaFuncAttributeMaxDynamicSharedMemorySize, GEMM_SMEM_BYTES);
    cudaFuncSetAttribute(gemm_mma_kernel<0, 1>,
        cudaFuncAttributeMaxDynamicSharedMemorySize, GEMM_SMEM_BYTES);
    cudaFuncSetAttribute(gemm_mma_kernel<0, 0>,
        cudaFuncAttributeMaxDynamicSharedMemorySize, GEMM_SMEM_BYTES);

    // ---- routing ----
    zero_counts_kernel<<<1, 32>>>();
    router_kernel<<<T_TOK, 256>>>(x, gw, cb);
    scan_kernel<<<1, 32>>>();
    build_perm_kernel<<<(T_TOK + 255) / 256, 256>>>();

    // ---- precondition: x -> fp16; weight transposes (gate_up paired) ----
    cvt_x_kernel<<<(T_TOK * HID) / 256, 256>>>(x);
    transpose_h_kernel<<<dim3(2 * IDIM / 32, HID / 32, NEXP), dim3(32, 8)>>>(
        wgu, p_wguT, HID, 2 * IDIM, (size_t)HID * 2 * IDIM, (size_t)HID * 2 * IDIM, IDIM);
    transpose_h_kernel<<<dim3(HID / 32, IDIM / 32, NEXP), dim3(32, 8)>>>(
        wdn, p_wdnT, IDIM, HID, (size_t)IDIM * HID, (size_t)IDIM * HID, 0);
    transpose_h_kernel<<<dim3(2 * ISH / 32, HID / 32, 1), dim3(32, 8)>>>(
        swgu, p_sguT, HID, 2 * ISH, 0, 0, ISH);
    transpose_h_kernel<<<dim3(HID / 32, ISH / 32, 1), dim3(32, 8)>>>(
        swdn, p_sdnT, ISH, HID, 0, 0, 0);

    // ---- routed experts ----
    // gate_up + fused SwiGLU -> g_ract (half)
    gemm_mma_kernel<2, 1><<<dim3(2 * IDIM / 128, 16, NEXP), 256, GEMM_SMEM_BYTES>>>(
        p_xh, HID, p_wguT, (size_t)2 * IDIM * HID, nullptr, p_ract, IDIM, 0);
    // down -> g_rdown (f32)
    gemm_mma_kernel<1, 0><<<dim3(HID / 128, 16, NEXP), 256, GEMM_SMEM_BYTES>>>(
        p_ract, IDIM, p_wdnT, (size_t)HID * IDIM, p_rdown, nullptr, HID, 0);

    // ---- shared expert ----
    gemm_mma_kernel<0, 1><<<dim3(2 * ISH / 128, T_TOK / 128, 1), 256, GEMM_SMEM_BYTES>>>(
        p_xh, HID, p_sguT, 0, nullptr, p_sact, ISH, T_TOK);
    gemm_mma_kernel<0, 0><<<dim3(HID / 128, T_TOK / 128, 1), 256, GEMM_SMEM_BYTES>>>(
        p_sact, ISH, p_sdnT, 0, p_sdown, nullptr, HID, T_TOK);

    // ---- combine: out = 2.5 * routed + shared ----
    combine_kernel<<<(T_TOK * HID) / 256, 256>>>(out, p_sdown);
}